// round 6
// baseline (speedup 1.0000x reference)
#include <cuda_runtime.h>
#include <cuda_bf16.h>

// NeRF volume-rendering composite — final form.
// Inputs (metadata order):
//   0: sigma_vals [N, S] f32   1: rgb_vals [N, S, 3] f32   2: dists [N, S] f32
//   3: z_vals [N, S] f32       4: bg_color [N, 3] f32
// Output: [N, 4] f32 (r, g, b, depth)
//
// One warp per ray; lane l owns samples [4l, 4l+4) -> all bulk loads are
// fully-coalesced LDG.128 streams (__ldcs: read-once, evict-first).
// 256-thread one-shot blocks (measured best: regs=32, occ ~92%).
// bg loaded warp-cooperatively up-front; epilogue stored by lanes 0-3.
// Measured at ~6.4 TB/s = GB300's path-independent LTS chip cap.

#ifndef NSAMP
#define NSAMP 128
#endif

__global__ __launch_bounds__(256) void raymarch_kernel(
    const float* __restrict__ sigma,
    const float* __restrict__ rgb,
    const float* __restrict__ dists,
    const float* __restrict__ z_vals,
    const float* __restrict__ bg,
    float* __restrict__ out,
    int n_rays)
{
    const int wib  = threadIdx.x >> 5;
    const int lane = threadIdx.x & 31;
    const int ray  = blockIdx.x * (blockDim.x >> 5) + wib;
    if (ray >= n_rays) return;

    const unsigned FULL = 0xFFFFFFFFu;

    // ---- coalesced front-batched streaming loads (7 independent LDGs) ----
    const float4* sig4 = reinterpret_cast<const float4*>(sigma  + (size_t)ray * NSAMP);
    const float4* dst4 = reinterpret_cast<const float4*>(dists  + (size_t)ray * NSAMP);
    const float4* zv4  = reinterpret_cast<const float4*>(z_vals + (size_t)ray * NSAMP);
    const float4* rg4  = reinterpret_cast<const float4*>(rgb    + (size_t)ray * NSAMP * 3);

    float4 s  = __ldcs(&sig4[lane]);
    float4 d  = __ldcs(&dst4[lane]);
    float4 z  = __ldcs(&zv4[lane]);
    float4 r0 = __ldcs(&rg4[3 * lane + 0]);   // s0.r s0.g s0.b s1.r
    float4 r1 = __ldcs(&rg4[3 * lane + 1]);   // s1.g s1.b s2.r s2.g
    float4 r2 = __ldcs(&rg4[3 * lane + 2]);   // s2.b s3.r s3.g s3.b
    // bg: warp-cooperative, lanes 0-2 read 3 consecutive floats (one sector)
    float bgv = (lane < 3) ? __ldg(&bg[(size_t)ray * 3 + lane]) : 0.0f;

    // ---- alpha and (1 - alpha + eps) ----
    float a0, a1, a2, a3, t0, t1, t2, t3, tau;
    tau = fmaxf(s.x, 0.0f) * d.x;  a0 = 1.0f - __expf(-tau);  t0 = 1.0f - a0 + 1e-10f;
    tau = fmaxf(s.y, 0.0f) * d.y;  a1 = 1.0f - __expf(-tau);  t1 = 1.0f - a1 + 1e-10f;
    tau = fmaxf(s.z, 0.0f) * d.z;  a2 = 1.0f - __expf(-tau);  t2 = 1.0f - a2 + 1e-10f;
    tau = fmaxf(s.w, 0.0f) * d.w;  a3 = 1.0f - __expf(-tau);  t3 = 1.0f - a3 + 1e-10f;

    // ---- local inclusive products ----
    float q0 = t0, q1 = q0 * t1, q2 = q1 * t2, q3 = q2 * t3;

    // ---- multiplicative inclusive warp scan of q3 ----
    float incl = q3;
    #pragma unroll
    for (int off = 1; off < 32; off <<= 1) {
        float v = __shfl_up_sync(FULL, incl, off);
        if (lane >= off) incl *= v;
    }
    float excl = __shfl_up_sync(FULL, incl, 1);
    if (lane == 0) excl = 1.0f;
    float no_hit = __shfl_sync(FULL, incl, 31);

    // ---- weights ----
    float w0 = a0 * excl;
    float w1 = a1 * (excl * q0);
    float w2 = a2 * (excl * q1);
    float w3 = a3 * (excl * q2);

    float cr = w0 * r0.x + w1 * r0.w + w2 * r1.z + w3 * r2.y;
    float cg = w0 * r0.y + w1 * r1.x + w2 * r1.w + w3 * r2.z;
    float cb = w0 * r0.z + w1 * r1.y + w2 * r2.x + w3 * r2.w;
    float dep = w0 * z.x + w1 * z.y + w2 * z.z + w3 * z.w;

    // ---- butterfly reductions: all lanes end with full sums ----
    #pragma unroll
    for (int off = 16; off > 0; off >>= 1) {
        cr  += __shfl_xor_sync(FULL, cr,  off);
        cg  += __shfl_xor_sync(FULL, cg,  off);
        cb  += __shfl_xor_sync(FULL, cb,  off);
        dep += __shfl_xor_sync(FULL, dep, off);
    }

    // ---- scattered store: lanes 0-3 write r,g,b,depth (one 16B sector) ----
    if (lane < 4) {
        float oval = dep;
        if (lane == 0) oval = fmaf(no_hit, bgv, cr);
        if (lane == 1) oval = fmaf(no_hit, bgv, cg);
        if (lane == 2) oval = fmaf(no_hit, bgv, cb);
        __stcs(&out[(size_t)ray * 4 + lane], oval);
    }
}

extern "C" void kernel_launch(void* const* d_in, const int* in_sizes, int n_in,
                              void* d_out, int out_size) {
    const float* sigma  = (const float*)d_in[0];
    const float* rgb    = (const float*)d_in[1];
    const float* dists  = (const float*)d_in[2];
    const float* z_vals = (const float*)d_in[3];
    const float* bg     = (const float*)d_in[4];
    float* out = (float*)d_out;

    int n_rays = in_sizes[4] / 3;        // bg_color is [N, 3]
    int threads = 256;                   // 8 warps = 8 rays per block
    int blocks = (n_rays + 7) / 8;
    raymarch_kernel<<<blocks, threads>>>(sigma, rgb, dists, z_vals, bg, out, n_rays);
}

// round 7
// speedup vs baseline: 1.0154x; 1.0154x over previous
#include <cuda_runtime.h>
#include <cuda_bf16.h>

// NeRF volume-rendering composite — converged final form (R2 configuration).
// Inputs (metadata order):
//   0: sigma_vals [N, S] f32   1: rgb_vals [N, S, 3] f32   2: dists [N, S] f32
//   3: z_vals [N, S] f32       4: bg_color [N, 3] f32
// Output: [N, 4] f32 (r, g, b, depth)
//
// One warp per ray; lane l owns samples [4l, 4l+4) -> all bulk loads are
// fully-coalesced LDG.128 streams with __ldcs (read-once, evict-first:
// 203 MB streamed through a 126 MB L2, don't fight for residency).
// 256-thread one-shot blocks, regs=32, occ ~92%.
// Measured ~6.4 TB/s = GB300's path-independent LTS chip cap; traffic is
// irreducible (every byte touched exactly once), so this is the roofline.

#ifndef NSAMP
#define NSAMP 128
#endif

__global__ __launch_bounds__(256, 4) void raymarch_kernel(
    const float* __restrict__ sigma,
    const float* __restrict__ rgb,
    const float* __restrict__ dists,
    const float* __restrict__ z_vals,
    const float* __restrict__ bg,
    float* __restrict__ out,
    int n_rays)
{
    const int warp_in_block = threadIdx.x >> 5;
    const int lane = threadIdx.x & 31;
    const int ray = blockIdx.x * (blockDim.x >> 5) + warp_in_block;
    if (ray >= n_rays) return;

    const unsigned FULL = 0xFFFFFFFFu;

    const float4* sig4 = reinterpret_cast<const float4*>(sigma  + (size_t)ray * NSAMP);
    const float4* dst4 = reinterpret_cast<const float4*>(dists  + (size_t)ray * NSAMP);
    const float4* zv4  = reinterpret_cast<const float4*>(z_vals + (size_t)ray * NSAMP);
    const float4* rg4  = reinterpret_cast<const float4*>(rgb    + (size_t)ray * NSAMP * 3);

    // ---- front-batched streaming loads: 6 independent LDG.128 in flight ----
    float4 s  = __ldcs(&sig4[lane]);
    float4 d  = __ldcs(&dst4[lane]);
    float4 z  = __ldcs(&zv4[lane]);
    float4 r0 = __ldcs(&rg4[3 * lane + 0]);   // s0.r s0.g s0.b s1.r
    float4 r1 = __ldcs(&rg4[3 * lane + 1]);   // s1.g s1.b s2.r s2.g
    float4 r2 = __ldcs(&rg4[3 * lane + 2]);   // s2.b s3.r s3.g s3.b

    // ---- alpha and (1 - alpha + eps) per sample ----
    float a0, a1, a2, a3;
    float t0, t1, t2, t3;
    {
        float tau;
        tau = fmaxf(s.x, 0.0f) * d.x;  a0 = 1.0f - __expf(-tau);  t0 = 1.0f - a0 + 1e-10f;
        tau = fmaxf(s.y, 0.0f) * d.y;  a1 = 1.0f - __expf(-tau);  t1 = 1.0f - a1 + 1e-10f;
        tau = fmaxf(s.z, 0.0f) * d.z;  a2 = 1.0f - __expf(-tau);  t2 = 1.0f - a2 + 1e-10f;
        tau = fmaxf(s.w, 0.0f) * d.w;  a3 = 1.0f - __expf(-tau);  t3 = 1.0f - a3 + 1e-10f;
    }

    // ---- local inclusive products ----
    float q0 = t0;
    float q1 = q0 * t1;
    float q2 = q1 * t2;
    float q3 = q2 * t3;   // product of this lane's 4 terms

    // ---- multiplicative inclusive warp scan of q3 ----
    float incl = q3;
    #pragma unroll
    for (int off = 1; off < 32; off <<= 1) {
        float v = __shfl_up_sync(FULL, incl, off);
        if (lane >= off) incl *= v;
    }
    // exclusive prefix (transmittance entering this lane's first sample)
    float excl = __shfl_up_sync(FULL, incl, 1);
    if (lane == 0) excl = 1.0f;

    // transmittance over ALL samples (no_hit) = lane 31's inclusive product
    float no_hit = __shfl_sync(FULL, incl, 31);

    // ---- weights and accumulation ----
    float w0 = a0 * excl;
    float w1 = a1 * (excl * q0);
    float w2 = a2 * (excl * q1);
    float w3 = a3 * (excl * q2);

    float cr = w0 * r0.x + w1 * r0.w + w2 * r1.z + w3 * r2.y;
    float cg = w0 * r0.y + w1 * r1.x + w2 * r1.w + w3 * r2.z;
    float cb = w0 * r0.z + w1 * r1.y + w2 * r2.x + w3 * r2.w;
    float dep = w0 * z.x + w1 * z.y + w2 * z.z + w3 * z.w;

    // ---- butterfly reductions (4 chains interleaved for ILP) ----
    #pragma unroll
    for (int off = 16; off > 0; off >>= 1) {
        cr  += __shfl_xor_sync(FULL, cr,  off);
        cg  += __shfl_xor_sync(FULL, cg,  off);
        cb  += __shfl_xor_sync(FULL, cb,  off);
        dep += __shfl_xor_sync(FULL, dep, off);
    }

    if (lane == 0) {
        const float* bgp = bg + (size_t)ray * 3;
        float4 o;
        o.x = cr + no_hit * __ldg(&bgp[0]);
        o.y = cg + no_hit * __ldg(&bgp[1]);
        o.z = cb + no_hit * __ldg(&bgp[2]);
        o.w = dep;
        __stcs(&reinterpret_cast<float4*>(out)[ray], o);
    }
}

extern "C" void kernel_launch(void* const* d_in, const int* in_sizes, int n_in,
                              void* d_out, int out_size) {
    const float* sigma  = (const float*)d_in[0];
    const float* rgb    = (const float*)d_in[1];
    const float* dists  = (const float*)d_in[2];
    const float* z_vals = (const float*)d_in[3];
    const float* bg     = (const float*)d_in[4];
    float* out = (float*)d_out;

    int n_rays = in_sizes[4] / 3;          // bg_color is [N, 3]
    int warps_per_block = 256 / 32;        // 8 rays per block
    int blocks = (n_rays + warps_per_block - 1) / warps_per_block;
    raymarch_kernel<<<blocks, 256>>>(sigma, rgb, dists, z_vals, bg, out, n_rays);
}